// round 7
// baseline (speedup 1.0000x reference)
#include <cuda_runtime.h>
#include <cuda_fp16.h>
#include <stdint.h>

#define B_ 256
#define R_ 192
#define C_ 96
#define O_ 16
#define I_ 20
#define BCH 8                   // batch elements per tile
#define NCH (B_ / BCH)          // 32 chunks
#define TILES (C_ * NCH)        // 3072
#define GRID 304                // persistent CTAs (2/SM on 152 SMs)
#define TILE_U4 (R_ * BCH * O_ / 8)   // 3072 uint4 = 48KB per tile

// Scratch (allocation-free rule: __device__ globals)
__device__ __half g_uhat[(size_t)R_ * C_ * B_ * O_];  // [R][C][B][O] fp16 ~151MB
__device__ float  g_xT[(size_t)R_ * I_ * B_];         // [R][I][B] transposed x
__device__ float  g_part[2][C_][R_][NCH];             // agreement partials

// ---- packed fp32x2 helpers ----
__device__ __forceinline__ unsigned long long pack2(float v) {
    unsigned long long r;
    asm("mov.b64 %0, {%1, %1};" : "=l"(r) : "f"(v));
    return r;
}
__device__ __forceinline__ void fma2(unsigned long long& d, unsigned long long a,
                                     unsigned long long b) {
    asm("fma.rn.f32x2 %0, %1, %2, %3;" : "=l"(d) : "l"(a), "l"(b), "l"(d));
}
__device__ __forceinline__ float2 unpack2(unsigned long long v) {
    float2 f;
    asm("mov.b64 {%0, %1}, %2;" : "=f"(f.x), "=f"(f.y) : "l"(v));
    return f;
}

// ---- cp.async helpers ----
__device__ __forceinline__ uint32_t smem_u32(const void* p) {
    return (uint32_t)__cvta_generic_to_shared(p);
}
__device__ __forceinline__ void cp_async16(uint32_t dst, const void* src) {
    asm volatile("cp.async.cg.shared.global [%0], [%1], 16;" :: "r"(dst), "l"(src)
                 : "memory");
}
__device__ __forceinline__ void cp_commit() {
    asm volatile("cp.async.commit_group;" ::: "memory");
}
template <int W> __device__ __forceinline__ void cp_wait() {
    asm volatile("cp.async.wait_group %0;" :: "n"(W) : "memory");
}

// ============================================================================
// Transpose x[b][r][i] -> xT[r][i][b].
// ============================================================================
__global__ void xpose_kernel(const float* __restrict__ x) {
    const int r = blockIdx.x;
    const int b = threadIdx.x;
    float t[I_];
#pragma unroll
    for (int q = 0; q < 5; q++) {
        float4 v = reinterpret_cast<const float4*>(x + ((size_t)b * R_ + r) * I_)[q];
        t[4 * q + 0] = v.x; t[4 * q + 1] = v.y; t[4 * q + 2] = v.z; t[4 * q + 3] = v.w;
    }
#pragma unroll
    for (int i = 0; i < I_; i++)
        g_xT[((size_t)r * I_ + i) * B_ + b] = t[i];
}

// ============================================================================
// u_hat[r][c][b][o] = sum_i W[r,c,o,i] * x[b,r,i]  (fp32 compute, fp16 store)
// ============================================================================
#define CPB 8
__global__ void __launch_bounds__(128) uhat_kernel(const float* __restrict__ W) {
    const int r  = blockIdx.x / (C_ / CPB);
    const int c0 = (blockIdx.x % (C_ / CPB)) * CPB;
    __shared__ __align__(16) float sW[CPB][I_][O_];
    const int tid = threadIdx.x;

    for (int idx = tid; idx < CPB * O_ * I_; idx += 128) {
        int cc  = idx / (O_ * I_);
        int rem = idx % (O_ * I_);
        int o = rem / I_;
        int i = rem % I_;
        sW[cc][i][o] = W[(((size_t)r * C_ + c0 + cc) * O_ + o) * I_ + i];
    }

    float xr[2][I_];
#pragma unroll
    for (int i = 0; i < I_; i++) {
        xr[0][i] = g_xT[((size_t)r * I_ + i) * B_ + tid];
        xr[1][i] = g_xT[((size_t)r * I_ + i) * B_ + tid + 128];
    }
    __syncthreads();

    for (int cc = 0; cc < CPB; cc++) {
        unsigned long long acc[2][O_ / 2];
#pragma unroll
        for (int h = 0; h < 2; h++)
#pragma unroll
            for (int op = 0; op < O_ / 2; op++) acc[h][op] = 0ULL;

#pragma unroll
        for (int i = 0; i < I_; i++) {
            unsigned long long x20 = pack2(xr[0][i]);
            unsigned long long x21 = pack2(xr[1][i]);
#pragma unroll
            for (int op = 0; op < O_ / 2; op++) {
                unsigned long long w2 =
                    *reinterpret_cast<const unsigned long long*>(&sW[cc][i][2 * op]);
                fma2(acc[0][op], w2, x20);
                fma2(acc[1][op], w2, x21);
            }
        }
#pragma unroll
        for (int h = 0; h < 2; h++) {
            const int b = tid + h * 128;
            __half2 hv[O_ / 2];
#pragma unroll
            for (int op = 0; op < O_ / 2; op++) {
                float2 f = unpack2(acc[h][op]);
                hv[op] = __floats2half2_rn(f.x, f.y);
            }
            uint4* dst = reinterpret_cast<uint4*>(
                g_uhat + (((size_t)r * C_ + c0 + cc) * B_ + b) * O_);
            dst[0] = *reinterpret_cast<uint4*>(&hv[0]);
            dst[1] = *reinterpret_cast<uint4*>(&hv[4]);
        }
    }
}

// ============================================================================
// Persistent fused routing kernel. 304 CTAs x 512 threads, double-buffered
// 48KB tiles [192r][8b][16o] fp16 (16 uint4 per r). Per tile:
//   prefetch next tile (cp.async) -> softmax (overlaps) -> wait -> phase1
//   (s+squash) -> phase2 (agreement partials from SMEM).
// ============================================================================
__global__ void __launch_bounds__(512, 2) fused_kernel(float* __restrict__ out, int it) {
    extern __shared__ __align__(16) uint4 su4[];   // 2 * TILE_U4
    __shared__ float2 sred[8][64];
    __shared__ float2 sv[64];                      // v: [8 b][8 o-pairs]
    __shared__ float  sc[R_];
    __shared__ float  smax[6], ssum[6];

    const int tid = threadIdx.x;
    const int lane = tid & 31, warp = tid >> 5;    // 16 warps
    const size_t rstride = (size_t)C_ * B_ * O_;   // halves per r step

    // ---- prologue: issue first tile into buffer 0 ----
    {
        const int t0 = blockIdx.x;
        const int c = t0 >> 5, ch = t0 & 31;
        const __half* gsrc = g_uhat + ((size_t)c * B_ + ch * BCH) * O_;
        const uint32_t sb = smem_u32(su4);
#pragma unroll
        for (int m = 0; m < 6; m++) {
            int idx = tid + 512 * m;
            int r = idx >> 4, q = idx & 15;
            cp_async16(sb + idx * 16, gsrc + (size_t)r * rstride + q * 8);
        }
        cp_commit();
    }

    int p = 0;
    for (int t = blockIdx.x; t < TILES; t += GRID, p ^= 1) {
        const int c = t >> 5, ch = t & 31;
        const int b0 = ch * BCH;
        const int tn = t + GRID;
        const bool has_next = tn < TILES;

        // ---- issue next tile into the other buffer ----
        if (has_next) {
            const int cn = tn >> 5, chn = tn & 31;
            const __half* gsrc = g_uhat + ((size_t)cn * B_ + chn * BCH) * O_;
            const uint32_t sb = smem_u32(su4 + (p ^ 1) * TILE_U4);
#pragma unroll
            for (int m = 0; m < 6; m++) {
                int idx = tid + 512 * m;
                int r = idx >> 4, q = idx & 15;
                cp_async16(sb + idx * 16, gsrc + (size_t)r * rstride + q * 8);
            }
            cp_commit();
        }

        // ---- softmax over r (overlaps in-flight loads) ----
        if (it > 0) {
            float lg = 0.f, e = 0.f;
            if (tid < R_) {
                const float4* q0 = reinterpret_cast<const float4*>(
                    &g_part[0][c][tid][0]);
#pragma unroll
                for (int j = 0; j < NCH / 4; j++) {
                    float4 v = q0[j];
                    lg += v.x + v.y + v.z + v.w;
                }
                if (it == 2) {
                    const float4* q1 = reinterpret_cast<const float4*>(
                        &g_part[1][c][tid][0]);
#pragma unroll
                    for (int j = 0; j < NCH / 4; j++) {
                        float4 v = q1[j];
                        lg += v.x + v.y + v.z + v.w;
                    }
                }
                lg *= (1.f / B_);
                float m = lg;
#pragma unroll
                for (int ofs = 16; ofs; ofs >>= 1)
                    m = fmaxf(m, __shfl_xor_sync(0xFFFFFFFFu, m, ofs));
                if (lane == 0) smax[warp] = m;
            }
            __syncthreads();
            if (tid < R_) {
                float mm = smax[0];
#pragma unroll
                for (int w = 1; w < 6; w++) mm = fmaxf(mm, smax[w]);
                e = expf(lg - mm);
                float s = e;
#pragma unroll
                for (int ofs = 16; ofs; ofs >>= 1)
                    s += __shfl_xor_sync(0xFFFFFFFFu, s, ofs);
                if (lane == 0) ssum[warp] = s;
            }
            __syncthreads();
            if (tid < R_) {
                float tot = 0.f;
#pragma unroll
                for (int w = 0; w < 6; w++) tot += ssum[w];
                sc[tid] = e / tot;
            }
        } else {
            if (tid < R_) sc[tid] = 1.f / R_;
        }

        // ---- wait for current tile ----
        if (has_next) cp_wait<1>(); else cp_wait<0>();
        __syncthreads();

        const uint4*   sub = su4 + p * TILE_U4;
        const __half2* su2 = reinterpret_cast<const __half2*>(sub);

        // ---- phase 1: s[b,o] = sum_r sc[r]*u[r,b,o] (24 r's per thread) ----
        {
            const int myidx = tid & 63;   // half2 index within r row (64 per r)
            const int rq = tid >> 6;      // 0..7
            float2 acc = make_float2(0.f, 0.f);
            const int r0 = rq * 24;
#pragma unroll 8
            for (int r = r0; r < r0 + 24; r++) {
                float2 u = __half22float2(su2[r * 64 + myidx]);
                float cv = sc[r];
                acc.x = fmaf(cv, u.x, acc.x);
                acc.y = fmaf(cv, u.y, acc.y);
            }
            sred[rq][myidx] = acc;
        }
        __syncthreads();

        if (tid < 64) {
            float2 s = sred[0][tid];
#pragma unroll
            for (int k = 1; k < 8; k++) { s.x += sred[k][tid].x; s.y += sred[k][tid].y; }
            float n2 = s.x * s.x + s.y * s.y;
#pragma unroll
            for (int ofs = 1; ofs < 8; ofs <<= 1)
                n2 += __shfl_xor_sync(0xFFFFFFFFu, n2, ofs);
            float scale = sqrtf(n2) / (1.f + n2);
            s.x *= scale; s.y *= scale;
            if (it == 2) {
                const int bl = tid >> 3, op = tid & 7;
                float2* dst = reinterpret_cast<float2*>(
                    out + (((size_t)(b0 + bl) * C_ + c) * O_)) + op;
                *dst = s;
            } else {
                sv[tid] = s;   // sv[b*8 + op]
            }
        }
        __syncthreads();

        // ---- phase 2: a[r] = sum_{b,o} u[r,b,o]*v[b,o] (tile from SMEM) ----
        // r row = 16 uint4; lanes 0-15 handle one r, lanes 16-31 another.
        // uint4 q covers (b = q>>1, o-half = q&1) -> v entries sv[q*4 + j].
        if (it != 2) {
            const int q  = lane & 15;
            const int rh = lane >> 4;     // 0 or 1
            float2 vv[4];
#pragma unroll
            for (int j = 0; j < 4; j++) vv[j] = sv[q * 4 + j];

#pragma unroll
            for (int k = 0; k < 6; k++) {
                const int r = warp + 16 * (2 * k + rh);
                uint4 u4 = sub[r * 16 + q];
                const __half2* h = reinterpret_cast<const __half2*>(&u4);
                float pacc = 0.f;
#pragma unroll
                for (int j = 0; j < 4; j++) {
                    float2 uf = __half22float2(h[j]);
                    pacc = fmaf(uf.x, vv[j].x, pacc);
                    pacc = fmaf(uf.y, vv[j].y, pacc);
                }
#pragma unroll
                for (int ofs = 8; ofs; ofs >>= 1)
                    pacc += __shfl_xor_sync(0xFFFFFFFFu, pacc, ofs);
                if ((lane & 15) == 0) g_part[it][c][r][ch] = pacc;
            }
        }
        __syncthreads();   // protect buffers/smem before next tile's issue
    }
}

extern "C" void kernel_launch(void* const* d_in, const int* in_sizes, int n_in,
                              void* d_out, int out_size) {
    const float* x = (const float*)d_in[0];  // [B,R,I]
    const float* W = (const float*)d_in[1];  // [R,C,O,I]
    float* out = (float*)d_out;              // [B,C,O]

    const int smem = 2 * TILE_U4 * sizeof(uint4);   // 98304
    cudaFuncSetAttribute(fused_kernel, cudaFuncAttributeMaxDynamicSharedMemorySize, smem);

    xpose_kernel<<<R_, 256>>>(x);
    uhat_kernel<<<R_ * (C_ / CPB), 128>>>(W);

    for (int it = 0; it < 3; it++)
        fused_kernel<<<GRID, 512, smem>>>(out, it);
}

// round 8
// speedup vs baseline: 1.3576x; 1.3576x over previous
#include <cuda_runtime.h>
#include <cuda_fp16.h>
#include <stdint.h>

#define B_ 256
#define R_ 192
#define C_ 96
#define O_ 16
#define I_ 20
#define BCH 8                   // batch elements per tile
#define NCH (B_ / BCH)          // 32 chunks
#define TILES (C_ * NCH)        // 3072
#define GRID 304                // persistent CTAs (2/SM on 152 SMs)
#define TILE_U4 (R_ * BCH * O_ / 8)   // 3072 uint4 = 48KB per tile
#define TILE_HALFS (R_ * BCH * O_)    // 24576 halves

// Scratch (allocation-free rule: __device__ globals)
// u_hat tile-contiguous: [c][ch][r][b'][o], each (c,ch) tile = 48KB sequential
__device__ uint4  g_uhat4[(size_t)TILES * TILE_U4];
__device__ float  g_xT[(size_t)R_ * I_ * B_];         // [R][I][B] transposed x
__device__ float  g_part[2][C_][R_][NCH];             // agreement partials
__device__ float  g_c[C_ * R_];                       // softmax coefficients [c][r]

// ---- packed fp32x2 helpers ----
__device__ __forceinline__ unsigned long long pack2(float v) {
    unsigned long long r;
    asm("mov.b64 %0, {%1, %1};" : "=l"(r) : "f"(v));
    return r;
}
__device__ __forceinline__ void fma2(unsigned long long& d, unsigned long long a,
                                     unsigned long long b) {
    asm("fma.rn.f32x2 %0, %1, %2, %3;" : "=l"(d) : "l"(a), "l"(b), "l"(d));
}
__device__ __forceinline__ float2 unpack2(unsigned long long v) {
    float2 f;
    asm("mov.b64 {%0, %1}, %2;" : "=f"(f.x), "=f"(f.y) : "l"(v));
    return f;
}

// ---- cp.async helpers ----
__device__ __forceinline__ uint32_t smem_u32(const void* p) {
    return (uint32_t)__cvta_generic_to_shared(p);
}
__device__ __forceinline__ void cp_async16(uint32_t dst, const void* src) {
    asm volatile("cp.async.cg.shared.global [%0], [%1], 16;" :: "r"(dst), "l"(src)
                 : "memory");
}
__device__ __forceinline__ void cp_commit() {
    asm volatile("cp.async.commit_group;" ::: "memory");
}
template <int W> __device__ __forceinline__ void cp_wait() {
    asm volatile("cp.async.wait_group %0;" :: "n"(W) : "memory");
}

// ============================================================================
// Transpose x[b][r][i] -> xT[r][i][b].
// ============================================================================
__global__ void xpose_kernel(const float* __restrict__ x) {
    const int r = blockIdx.x;
    const int b = threadIdx.x;
    float t[I_];
#pragma unroll
    for (int q = 0; q < 5; q++) {
        float4 v = reinterpret_cast<const float4*>(x + ((size_t)b * R_ + r) * I_)[q];
        t[4 * q + 0] = v.x; t[4 * q + 1] = v.y; t[4 * q + 2] = v.z; t[4 * q + 3] = v.w;
    }
#pragma unroll
    for (int i = 0; i < I_; i++)
        g_xT[((size_t)r * I_ + i) * B_ + b] = t[i];
}

// ============================================================================
// u_hat[(c,ch)][r][b'][o] = sum_i W[r,c,o,i] * x[b,r,i]
// fp32 compute (fp32x2 pipe), fp16 store into tile-contiguous layout.
// ============================================================================
#define CPB 8
__global__ void __launch_bounds__(128) uhat_kernel(const float* __restrict__ W) {
    const int r  = blockIdx.x / (C_ / CPB);
    const int c0 = (blockIdx.x % (C_ / CPB)) * CPB;
    __shared__ __align__(16) float sW[CPB][I_][O_];
    const int tid = threadIdx.x;

    for (int idx = tid; idx < CPB * O_ * I_; idx += 128) {
        int cc  = idx / (O_ * I_);
        int rem = idx % (O_ * I_);
        int o = rem / I_;
        int i = rem % I_;
        sW[cc][i][o] = W[(((size_t)r * C_ + c0 + cc) * O_ + o) * I_ + i];
    }

    float xr[2][I_];
#pragma unroll
    for (int i = 0; i < I_; i++) {
        xr[0][i] = g_xT[((size_t)r * I_ + i) * B_ + tid];
        xr[1][i] = g_xT[((size_t)r * I_ + i) * B_ + tid + 128];
    }
    __syncthreads();

    __half* uh = reinterpret_cast<__half*>(g_uhat4);

    for (int cc = 0; cc < CPB; cc++) {
        unsigned long long acc[2][O_ / 2];
#pragma unroll
        for (int h = 0; h < 2; h++)
#pragma unroll
            for (int op = 0; op < O_ / 2; op++) acc[h][op] = 0ULL;

#pragma unroll
        for (int i = 0; i < I_; i++) {
            unsigned long long x20 = pack2(xr[0][i]);
            unsigned long long x21 = pack2(xr[1][i]);
#pragma unroll
            for (int op = 0; op < O_ / 2; op++) {
                unsigned long long w2 =
                    *reinterpret_cast<const unsigned long long*>(&sW[cc][i][2 * op]);
                fma2(acc[0][op], w2, x20);
                fma2(acc[1][op], w2, x21);
            }
        }
#pragma unroll
        for (int h = 0; h < 2; h++) {
            const int b = tid + h * 128;
            const int ch = b >> 3, bl = b & 7;
            __half2 hv[O_ / 2];
#pragma unroll
            for (int op = 0; op < O_ / 2; op++) {
                float2 f = unpack2(acc[h][op]);
                hv[op] = __floats2half2_rn(f.x, f.y);
            }
            uint4* dst = reinterpret_cast<uint4*>(
                uh + ((size_t)(c0 + cc) * NCH + ch) * TILE_HALFS
                   + (size_t)r * (BCH * O_) + bl * O_);
            dst[0] = *reinterpret_cast<uint4*>(&hv[0]);
            dst[1] = *reinterpret_cast<uint4*>(&hv[4]);
        }
    }
}

// ============================================================================
// Softmax over r of accumulated logits -> g_c[c][r]. One block per c.
// ============================================================================
__global__ void softmax_kernel(int it) {
    const int c = blockIdx.x;
    const int tid = threadIdx.x;           // = r
    const int lane = tid & 31, warp = tid >> 5;
    __shared__ float sm[6], ssum[6];

    float lg = 0.f;
    {
        const float4* q0 = reinterpret_cast<const float4*>(&g_part[0][c][tid][0]);
#pragma unroll
        for (int j = 0; j < NCH / 4; j++) {
            float4 v = q0[j];
            lg += v.x + v.y + v.z + v.w;
        }
        if (it == 2) {
            const float4* q1 = reinterpret_cast<const float4*>(&g_part[1][c][tid][0]);
#pragma unroll
            for (int j = 0; j < NCH / 4; j++) {
                float4 v = q1[j];
                lg += v.x + v.y + v.z + v.w;
            }
        }
        lg *= (1.f / B_);
    }

    float m = lg;
#pragma unroll
    for (int ofs = 16; ofs; ofs >>= 1) m = fmaxf(m, __shfl_xor_sync(0xFFFFFFFFu, m, ofs));
    if (lane == 0) sm[warp] = m;
    __syncthreads();
    float mm = sm[0];
#pragma unroll
    for (int w = 1; w < 6; w++) mm = fmaxf(mm, sm[w]);

    float e = expf(lg - mm);
    float s = e;
#pragma unroll
    for (int ofs = 16; ofs; ofs >>= 1) s += __shfl_xor_sync(0xFFFFFFFFu, s, ofs);
    if (lane == 0) ssum[warp] = s;
    __syncthreads();
    float tot = 0.f;
#pragma unroll
    for (int w = 0; w < 6; w++) tot += ssum[w];

    g_c[c * R_ + tid] = e / tot;
}

// ============================================================================
// Persistent fused routing kernel. 304 CTAs x 512 threads, double-buffered
// contiguous 48KB tiles. Per tile:
//   prefetch next tile (cp.async, sequential addresses) + stage sc ->
//   wait -> phase1 (s+squash) -> phase2 (agreement partials from SMEM).
// ============================================================================
__global__ void __launch_bounds__(512, 2) fused_kernel(float* __restrict__ out, int it) {
    extern __shared__ __align__(16) uint4 su4[];   // 2 * TILE_U4
    __shared__ float2 sred[8][64];
    __shared__ float2 sv[64];                      // v: [8 b][8 o-pairs]
    __shared__ float  sc[R_];

    const int tid = threadIdx.x;
    const int lane = tid & 31, warp = tid >> 5;    // 16 warps

    // ---- prologue: issue first tile into buffer 0 ----
    {
        const uint4* gsrc = g_uhat4 + (size_t)blockIdx.x * TILE_U4;
        const uint32_t sb = smem_u32(su4);
#pragma unroll
        for (int m = 0; m < 6; m++) {
            int idx = tid + 512 * m;
            cp_async16(sb + idx * 16, gsrc + idx);
        }
        cp_commit();
    }

    int p = 0;
    for (int t = blockIdx.x; t < TILES; t += GRID, p ^= 1) {
        const int c = t >> 5, ch = t & 31;
        const int b0 = ch * BCH;
        const bool has_next = (t + GRID) < TILES;

        // ---- issue next tile into the other buffer ----
        if (has_next) {
            const uint4* gsrc = g_uhat4 + (size_t)(t + GRID) * TILE_U4;
            const uint32_t sb = smem_u32(su4 + (p ^ 1) * TILE_U4);
#pragma unroll
            for (int m = 0; m < 6; m++) {
                int idx = tid + 512 * m;
                cp_async16(sb + idx * 16, gsrc + idx);
            }
            cp_commit();
        }

        // ---- stage softmax coefficients (published by barrier below) ----
        if (tid < R_) sc[tid] = (it == 0) ? (1.f / R_) : g_c[c * R_ + tid];

        // ---- wait for current tile ----
        if (has_next) cp_wait<1>(); else cp_wait<0>();
        __syncthreads();

        const uint4*   sub = su4 + p * TILE_U4;
        const __half2* su2 = reinterpret_cast<const __half2*>(sub);

        // ---- phase 1: s[b,o] = sum_r sc[r]*u[r,b,o] (24 r's per thread) ----
        {
            const int myidx = tid & 63;   // half2 index within r row (64 per r)
            const int rq = tid >> 6;      // 0..7
            float2 acc = make_float2(0.f, 0.f);
            const int r0 = rq * 24;
#pragma unroll 8
            for (int r = r0; r < r0 + 24; r++) {
                float2 u = __half22float2(su2[r * 64 + myidx]);
                float cv = sc[r];
                acc.x = fmaf(cv, u.x, acc.x);
                acc.y = fmaf(cv, u.y, acc.y);
            }
            sred[rq][myidx] = acc;
        }
        __syncthreads();

        if (tid < 64) {
            float2 s = sred[0][tid];
#pragma unroll
            for (int k = 1; k < 8; k++) { s.x += sred[k][tid].x; s.y += sred[k][tid].y; }
            float n2 = s.x * s.x + s.y * s.y;
#pragma unroll
            for (int ofs = 1; ofs < 8; ofs <<= 1)
                n2 += __shfl_xor_sync(0xFFFFFFFFu, n2, ofs);
            float scale = sqrtf(n2) / (1.f + n2);
            s.x *= scale; s.y *= scale;
            if (it == 2) {
                const int bl = tid >> 3, op = tid & 7;
                float2* dst = reinterpret_cast<float2*>(
                    out + (((size_t)(b0 + bl) * C_ + c) * O_)) + op;
                *dst = s;
            } else {
                sv[tid] = s;   // sv[b*8 + op]
            }
        }
        __syncthreads();

        // ---- phase 2: a[r] = sum_{b,o} u[r,b,o]*v[b,o] (tile from SMEM) ----
        // r row = 16 uint4; lanes 0-15 handle one r, lanes 16-31 another.
        // uint4 q covers (b = q>>1, o-half = q&1) -> v entries sv[q*4 + j].
        if (it != 2) {
            const int q  = lane & 15;
            const int rh = lane >> 4;     // 0 or 1
            float2 vv[4];
#pragma unroll
            for (int j = 0; j < 4; j++) vv[j] = sv[q * 4 + j];

#pragma unroll
            for (int k = 0; k < 6; k++) {
                const int r = warp + 16 * (2 * k + rh);
                uint4 u4 = sub[r * 16 + q];
                const __half2* h = reinterpret_cast<const __half2*>(&u4);
                float pacc = 0.f;
#pragma unroll
                for (int j = 0; j < 4; j++) {
                    float2 uf = __half22float2(h[j]);
                    pacc = fmaf(uf.x, vv[j].x, pacc);
                    pacc = fmaf(uf.y, vv[j].y, pacc);
                }
#pragma unroll
                for (int ofs = 8; ofs; ofs >>= 1)
                    pacc += __shfl_xor_sync(0xFFFFFFFFu, pacc, ofs);
                if ((lane & 15) == 0) g_part[it][c][r][ch] = pacc;
            }
        }
        __syncthreads();   // protect buffers/smem before next tile's issue
    }
}

extern "C" void kernel_launch(void* const* d_in, const int* in_sizes, int n_in,
                              void* d_out, int out_size) {
    const float* x = (const float*)d_in[0];  // [B,R,I]
    const float* W = (const float*)d_in[1];  // [R,C,O,I]
    float* out = (float*)d_out;              // [B,C,O]

    const int smem = 2 * TILE_U4 * sizeof(uint4);   // 98304
    cudaFuncSetAttribute(fused_kernel, cudaFuncAttributeMaxDynamicSharedMemorySize, smem);

    xpose_kernel<<<R_, 256>>>(x);
    uhat_kernel<<<R_ * (C_ / CPB), 128>>>(W);

    for (int it = 0; it < 3; it++) {
        if (it > 0) softmax_kernel<<<C_, 192>>>(it);
        fused_kernel<<<GRID, 512, smem>>>(out, it);
    }
}

// round 9
// speedup vs baseline: 1.7855x; 1.3151x over previous
#include <cuda_runtime.h>
#include <cuda_fp16.h>
#include <stdint.h>

#define B_ 256
#define R_ 192
#define C_ 96
#define O_ 16
#define I_ 20
#define IP 24                   // I padded for mma (zeros)
#define BCH 8                   // batch elements per tile
#define NCH (B_ / BCH)          // 32 chunks
#define TILES (C_ * NCH)        // 3072
#define GRID 304                // persistent CTAs (2/SM on 152 SMs)
#define TILE_U4 (R_ * BCH * O_ / 8)   // 3072 uint4 = 48KB per tile
#define TILE_HALFS (R_ * BCH * O_)    // 24576 halves

// Scratch (allocation-free rule: __device__ globals)
__device__ uint4  g_uhat4[(size_t)TILES * TILE_U4];   // tile-contiguous u_hat fp16
__device__ __half g_x16[(size_t)R_ * B_ * IP];        // x fp16 [r][b][24]
__device__ __half g_W16[(size_t)R_ * C_ * O_ * IP];   // W fp16 [r][c][o][24]
__device__ float  g_part[2][C_][R_][NCH];             // agreement partials
__device__ float  g_c[C_ * R_];                       // softmax coefficients [c][r]

// ---- packed fp32x2 helpers ----
__device__ __forceinline__ unsigned long long pack2(float v) {
    unsigned long long r;
    asm("mov.b64 %0, {%1, %1};" : "=l"(r) : "f"(v));
    return r;
}
__device__ __forceinline__ void fma2(unsigned long long& d, unsigned long long a,
                                     unsigned long long b) {
    asm("fma.rn.f32x2 %0, %1, %2, %3;" : "=l"(d) : "l"(a), "l"(b), "l"(d));
}
__device__ __forceinline__ float2 unpack2(unsigned long long v) {
    float2 f;
    asm("mov.b64 {%0, %1}, %2;" : "=f"(f.x), "=f"(f.y) : "l"(v));
    return f;
}

// ---- cp.async helpers ----
__device__ __forceinline__ uint32_t smem_u32(const void* p) {
    return (uint32_t)__cvta_generic_to_shared(p);
}
__device__ __forceinline__ void cp_async16(uint32_t dst, const void* src) {
    asm volatile("cp.async.cg.shared.global [%0], [%1], 16;" :: "r"(dst), "l"(src)
                 : "memory");
}
__device__ __forceinline__ void cp_commit() {
    asm volatile("cp.async.commit_group;" ::: "memory");
}
template <int W> __device__ __forceinline__ void cp_wait() {
    asm volatile("cp.async.wait_group %0;" :: "n"(W) : "memory");
}

// ---- mma helpers (fp16 in, fp32 accum) ----
__device__ __forceinline__ void mma16816(float d[4], uint32_t a0, uint32_t a1,
                                         uint32_t a2, uint32_t a3,
                                         uint32_t b0, uint32_t b1) {
    asm volatile(
        "mma.sync.aligned.m16n8k16.row.col.f32.f16.f16.f32 "
        "{%0,%1,%2,%3},{%4,%5,%6,%7},{%8,%9},{%0,%1,%2,%3};"
        : "+f"(d[0]), "+f"(d[1]), "+f"(d[2]), "+f"(d[3])
        : "r"(a0), "r"(a1), "r"(a2), "r"(a3), "r"(b0), "r"(b1));
}
__device__ __forceinline__ void mma1688(float d[4], uint32_t a0, uint32_t a1,
                                        uint32_t b0) {
    asm volatile(
        "mma.sync.aligned.m16n8k8.row.col.f32.f16.f16.f32 "
        "{%0,%1,%2,%3},{%4,%5},{%6},{%0,%1,%2,%3};"
        : "+f"(d[0]), "+f"(d[1]), "+f"(d[2]), "+f"(d[3])
        : "r"(a0), "r"(a1), "r"(b0));
}

// ============================================================================
// Convert x[b][r][i] f32 -> x16[r][b][24] fp16 (i padded with zeros).
// ============================================================================
__global__ void convx_kernel(const float* __restrict__ x) {
    const int r = blockIdx.x;
    const int b = threadIdx.x;
    const float4* src = reinterpret_cast<const float4*>(x + ((size_t)b * R_ + r) * I_);
    __half2 h[12];
#pragma unroll
    for (int q = 0; q < 5; q++) {
        float4 v = src[q];
        h[2 * q]     = __floats2half2_rn(v.x, v.y);
        h[2 * q + 1] = __floats2half2_rn(v.z, v.w);
    }
    h[10] = __floats2half2_rn(0.f, 0.f);
    h[11] = __floats2half2_rn(0.f, 0.f);
    uint4* dst = reinterpret_cast<uint4*>(g_x16 + ((size_t)r * B_ + b) * IP);
    dst[0] = *reinterpret_cast<uint4*>(&h[0]);
    dst[1] = *reinterpret_cast<uint4*>(&h[4]);
    dst[2] = *reinterpret_cast<uint4*>(&h[8]);
}

// ============================================================================
// Convert W[r][c][o][i] f32 -> W16[r][c][o][24] fp16 (padded).
// ============================================================================
__global__ void convw_kernel(const float* __restrict__ W) {
    const int idx = blockIdx.x * 256 + threadIdx.x;   // (r,c,o) flat, 294912
    const float4* src = reinterpret_cast<const float4*>(W + (size_t)idx * I_);
    __half2 h[12];
#pragma unroll
    for (int q = 0; q < 5; q++) {
        float4 v = src[q];
        h[2 * q]     = __floats2half2_rn(v.x, v.y);
        h[2 * q + 1] = __floats2half2_rn(v.z, v.w);
    }
    h[10] = __floats2half2_rn(0.f, 0.f);
    h[11] = __floats2half2_rn(0.f, 0.f);
    uint4* dst = reinterpret_cast<uint4*>(g_W16 + (size_t)idx * IP);
    dst[0] = *reinterpret_cast<uint4*>(&h[0]);
    dst[1] = *reinterpret_cast<uint4*>(&h[4]);
    dst[2] = *reinterpret_cast<uint4*>(&h[8]);
}

// ============================================================================
// u_hat via tensor cores. Block = (r, 8 c's), 256 threads = 8 warps (1 c each).
// A = x[r] (M=16 b rows), B = W[r][c] (N=8 o cols, 2 n-tiles), K=24 (16+8).
// D[16b][8o] fp32 -> fp16 -> tile-contiguous g_uhat4.
// ============================================================================
__global__ void __launch_bounds__(256) uhat_mma_kernel() {
    const int r  = blockIdx.x / (C_ / 8);
    const int c0 = (blockIdx.x % (C_ / 8)) * 8;
    __shared__ __align__(16) __half xs[B_ * IP];      // [b][24]  12288B
    __shared__ __align__(16) __half ws[8 * O_ * IP];  // [cc][o][24] 6144B
    const int tid = threadIdx.x;
    const int lane = tid & 31, w = tid >> 5;

    {
        const uint4* gx = reinterpret_cast<const uint4*>(g_x16 + (size_t)r * B_ * IP);
        uint4* sx = reinterpret_cast<uint4*>(xs);
#pragma unroll
        for (int m = 0; m < 3; m++) sx[tid + 256 * m] = gx[tid + 256 * m];
        const uint4* gw = reinterpret_cast<const uint4*>(
            g_W16 + ((size_t)r * C_ + c0) * O_ * IP);
        uint4* sw = reinterpret_cast<uint4*>(ws);
        if (tid < 128) { sw[tid] = gw[tid]; sw[tid + 128] = gw[tid + 128]; }
        else { int t = tid - 128; sw[t + 256] = gw[t + 256]; }
    }
    __syncthreads();

    const uint32_t* xs32 = reinterpret_cast<const uint32_t*>(xs);
    const uint32_t* ws32 = reinterpret_cast<const uint32_t*>(ws);
    __half* uh = reinterpret_cast<__half*>(g_uhat4);

    // B fragments (W) per warp: 2 n-tiles x {b0,b1 (k16), bk8}
    uint32_t bf[2][3];
#pragma unroll
    for (int nt = 0; nt < 2; nt++) {
        int base = (w * 16 + nt * 8 + (lane >> 2)) * 12 + (lane & 3);
        bf[nt][0] = ws32[base];
        bf[nt][1] = ws32[base + 4];
        bf[nt][2] = ws32[base + 8];
    }

    const int c = c0 + w;
#pragma unroll 4
    for (int bt = 0; bt < 16; bt++) {
        const int row = bt * 16 + (lane >> 2);
        const int a0i = row * 12 + (lane & 3);
        const int a1i = a0i + 96;   // row + 8
        uint32_t a0 = xs32[a0i], a1 = xs32[a1i];
        uint32_t a2 = xs32[a0i + 4], a3 = xs32[a1i + 4];
        uint32_t a4 = xs32[a0i + 8], a5 = xs32[a1i + 8];

#pragma unroll
        for (int nt = 0; nt < 2; nt++) {
            float d[4] = {0.f, 0.f, 0.f, 0.f};
            mma16816(d, a0, a1, a2, a3, bf[nt][0], bf[nt][1]);
            mma1688(d, a4, a5, bf[nt][2]);
            // D[b=row][o = nt*8 + 2*(lane&3) + {0,1}] = d0,d1 ; row+8 -> d2,d3
            __half2 h01 = __floats2half2_rn(d[0], d[1]);
            __half2 h23 = __floats2half2_rn(d[2], d[3]);
            const int o2 = nt * 8 + (lane & 3) * 2;
            const int blo = row, bhi = row + 8;
            size_t alo = ((size_t)(c * NCH + (blo >> 3))) * TILE_HALFS
                       + (size_t)r * 128 + (blo & 7) * 16 + o2;
            size_t ahi = ((size_t)(c * NCH + (bhi >> 3))) * TILE_HALFS
                       + (size_t)r * 128 + (bhi & 7) * 16 + o2;
            *reinterpret_cast<__half2*>(uh + alo) = h01;
            *reinterpret_cast<__half2*>(uh + ahi) = h23;
        }
    }
}

// ============================================================================
// Softmax over r of accumulated logits -> g_c[c][r]. One block per c.
// ============================================================================
__global__ void softmax_kernel(int it) {
    const int c = blockIdx.x;
    const int tid = threadIdx.x;           // = r
    const int lane = tid & 31, warp = tid >> 5;
    __shared__ float sm[6], ssum[6];

    float lg = 0.f;
    {
        const float4* q0 = reinterpret_cast<const float4*>(&g_part[0][c][tid][0]);
#pragma unroll
        for (int j = 0; j < NCH / 4; j++) {
            float4 v = q0[j];
            lg += v.x + v.y + v.z + v.w;
        }
        if (it == 2) {
            const float4* q1 = reinterpret_cast<const float4*>(&g_part[1][c][tid][0]);
#pragma unroll
            for (int j = 0; j < NCH / 4; j++) {
                float4 v = q1[j];
                lg += v.x + v.y + v.z + v.w;
            }
        }
        lg *= (1.f / B_);
    }

    float m = lg;
#pragma unroll
    for (int ofs = 16; ofs; ofs >>= 1) m = fmaxf(m, __shfl_xor_sync(0xFFFFFFFFu, m, ofs));
    if (lane == 0) sm[warp] = m;
    __syncthreads();
    float mm = sm[0];
#pragma unroll
    for (int w = 1; w < 6; w++) mm = fmaxf(mm, sm[w]);

    float e = expf(lg - mm);
    float s = e;
#pragma unroll
    for (int ofs = 16; ofs; ofs >>= 1) s += __shfl_xor_sync(0xFFFFFFFFu, s, ofs);
    if (lane == 0) ssum[warp] = s;
    __syncthreads();
    float tot = 0.f;
#pragma unroll
    for (int w = 0; w < 6; w++) tot += ssum[w];

    g_c[c * R_ + tid] = e / tot;
}

// ============================================================================
// Persistent fused routing kernel. 304 CTAs x 512 threads, double-buffered
// contiguous 48KB tiles. phase1 now uses LDS.128 + in-warp fold.
// ============================================================================
__global__ void __launch_bounds__(512, 2) fused_kernel(float* __restrict__ out, int it) {
    extern __shared__ __align__(16) uint4 su4[];   // 2 * TILE_U4
    __shared__ float sred[16][16][8];              // [warp-group][q][o-offset] 8KB
    __shared__ float svf[BCH * O_];                // v as [b][o]
    __shared__ float sc[R_];

    const int tid = threadIdx.x;
    const int lane = tid & 31, warp = tid >> 5;    // 16 warps

    // ---- prologue: issue first tile into buffer 0 ----
    {
        const uint4* gsrc = g_uhat4 + (size_t)blockIdx.x * TILE_U4;
        const uint32_t sb = smem_u32(su4);
#pragma unroll
        for (int m = 0; m < 6; m++) {
            int idx = tid + 512 * m;
            cp_async16(sb + idx * 16, gsrc + idx);
        }
        cp_commit();
    }

    int p = 0;
    for (int t = blockIdx.x; t < TILES; t += GRID, p ^= 1) {
        const int c = t >> 5, ch = t & 31;
        const int b0 = ch * BCH;
        const bool has_next = (t + GRID) < TILES;

        // ---- issue next tile into the other buffer ----
        if (has_next) {
            const uint4* gsrc = g_uhat4 + (size_t)(t + GRID) * TILE_U4;
            const uint32_t sb = smem_u32(su4 + (p ^ 1) * TILE_U4);
#pragma unroll
            for (int m = 0; m < 6; m++) {
                int idx = tid + 512 * m;
                cp_async16(sb + idx * 16, gsrc + idx);
            }
            cp_commit();
        }

        // ---- stage softmax coefficients ----
        if (tid < R_) sc[tid] = (it == 0) ? (1.f / R_) : g_c[c * R_ + tid];

        // ---- wait for current tile ----
        if (has_next) cp_wait<1>(); else cp_wait<0>();
        __syncthreads();

        const uint4* sub = su4 + p * TILE_U4;

        // ---- phase 1: s[b,o] = sum_r sc[r]*u[r,b,o], LDS.128 per thread ----
        {
            const int rg = tid >> 4;      // 0..31, r = rg*6 + j
            const int q  = tid & 15;      // uint4 within row
            unsigned long long acc[4] = {0ULL, 0ULL, 0ULL, 0ULL};
#pragma unroll
            for (int j = 0; j < 6; j++) {
                const int r = rg * 6 + j;
                uint4 u4 = sub[r * 16 + q];
                const __half2* h = reinterpret_cast<const __half2*>(&u4);
                unsigned long long cv = pack2(sc[r]);
#pragma unroll
                for (int s = 0; s < 4; s++) {
                    float2 uf = __half22float2(h[s]);
                    unsigned long long u2;
                    asm("mov.b64 %0, {%1, %2};" : "=l"(u2) : "f"(uf.x), "f"(uf.y));
                    fma2(acc[s], u2, cv);
                }
            }
            // fold lane l with l^16 (same q, adjacent rg) via shfl
            float af[8];
#pragma unroll
            for (int s = 0; s < 4; s++) {
                float2 f = unpack2(acc[s]);
                af[2 * s] = f.x; af[2 * s + 1] = f.y;
            }
#pragma unroll
            for (int s = 0; s < 8; s++)
                af[s] += __shfl_xor_sync(0xFFFFFFFFu, af[s], 16);
            if (lane < 16) {
#pragma unroll
                for (int s = 0; s < 8; s++) sred[warp][q][s] = af[s];
            }
        }
        __syncthreads();

        // ---- reduce over 16 groups + squash (128 threads) ----
        if (tid < 128) {
            const int q = tid >> 3, sl = tid & 7;
            float s = 0.f;
#pragma unroll
            for (int g = 0; g < 16; g++) s += sred[g][q][sl];
            const int b = q >> 1;
            const int o = (q & 1) * 8 + sl;
            float n2 = s * s;
#pragma unroll
            for (int ofs = 1; ofs < 16; ofs <<= 1)
                n2 += __shfl_xor_sync(0xFFFFFFFFu, n2, ofs);
            float scale = sqrtf(n2) / (1.f + n2);
            s *= scale;
            if (it == 2)
                out[(((size_t)(b0 + b)) * C_ + c) * O_ + o] = s;
            else
                svf[b * O_ + o] = s;
        }
        __syncthreads();

        // ---- phase 2: a[r] = sum_{b,o} u[r,b,o]*v[b,o] (tile from SMEM) ----
        if (it != 2) {
            const int q  = lane & 15;
            const int rh = lane >> 4;     // 0 or 1
            const float2* sv2 = reinterpret_cast<const float2*>(svf);
            float2 vv[4];
#pragma unroll
            for (int j = 0; j < 4; j++)
                vv[j] = sv2[(q >> 1) * 8 + (q & 1) * 4 + j];

#pragma unroll
            for (int k = 0; k < 6; k++) {
                const int r = warp + 16 * (2 * k + rh);
                uint4 u4 = sub[r * 16 + q];
                const __half2* h = reinterpret_cast<const __half2*>(&u4);
                float pacc = 0.f;
#pragma unroll
                for (int j = 0; j < 4; j++) {
                    float2 uf = __half22float2(h[j]);
                    pacc = fmaf(uf.x, vv[j].x, pacc);
                    pacc = fmaf(uf.y, vv[j].y, pacc);
                }
#pragma unroll
                for (int ofs = 8; ofs; ofs >>= 1)
                    pacc += __shfl_xor_sync(0xFFFFFFFFu, pacc, ofs);
                if ((lane & 15) == 0) g_part[it][c][r][ch] = pacc;
            }
        }
        __syncthreads();   // protect buffers/smem before next tile's issue
    }
}

extern "C" void kernel_launch(void* const* d_in, const int* in_sizes, int n_in,
                              void* d_out, int out_size) {
    const float* x = (const float*)d_in[0];  // [B,R,I]
    const float* W = (const float*)d_in[1];  // [R,C,O,I]
    float* out = (float*)d_out;              // [B,C,O]

    const int smem = 2 * TILE_U4 * sizeof(uint4);   // 98304
    cudaFuncSetAttribute(fused_kernel, cudaFuncAttributeMaxDynamicSharedMemorySize, smem);

    convx_kernel<<<R_, 256>>>(x);
    convw_kernel<<<(R_ * C_ * O_) / 256, 256>>>(W);
    uhat_mma_kernel<<<R_ * (C_ / 8), 256>>>();

    for (int it = 0; it < 3; it++) {
        if (it > 0) softmax_kernel<<<C_, 192>>>(it);
        fused_kernel<<<GRID, 512, smem>>>(out, it);
    }
}

// round 10
// speedup vs baseline: 1.9007x; 1.0646x over previous
#include <cuda_runtime.h>
#include <cuda_fp16.h>
#include <stdint.h>

#define B_ 256
#define R_ 192
#define C_ 96
#define O_ 16
#define I_ 20
#define IP 24                   // I padded for mma (zeros)
#define BCH 8                   // batch elements per tile
#define NCH (B_ / BCH)          // 32 chunks
#define TILES (C_ * NCH)        // 3072
#define GRID 304                // persistent CTAs (2/SM on 152 SMs)
#define TILE_U4 (R_ * BCH * O_ / 8)   // 3072 uint4 = 48KB per tile
#define TILE_HALFS (R_ * BCH * O_)    // 24576 halves
#define TILE_BYTES (TILE_U4 * 16)     // 49152

// Scratch (allocation-free rule: __device__ globals)
__device__ uint4  g_uhat4[(size_t)TILES * TILE_U4];   // tile-contiguous u_hat fp16
__device__ __half g_x16[(size_t)R_ * B_ * IP];        // x fp16 [r][b][24]
__device__ __half g_W16[(size_t)R_ * C_ * O_ * IP];   // W fp16 [r][c][o][24]
__device__ float  g_part[2][C_][R_][NCH];             // agreement partials
__device__ float  g_c[C_ * R_];                       // softmax coefficients [c][r]

// ---- packed fp32x2 helpers ----
__device__ __forceinline__ unsigned long long pack2(float v) {
    unsigned long long r;
    asm("mov.b64 %0, {%1, %1};" : "=l"(r) : "f"(v));
    return r;
}
__device__ __forceinline__ void fma2(unsigned long long& d, unsigned long long a,
                                     unsigned long long b) {
    asm("fma.rn.f32x2 %0, %1, %2, %3;" : "=l"(d) : "l"(a), "l"(b), "l"(d));
}
__device__ __forceinline__ float2 unpack2(unsigned long long v) {
    float2 f;
    asm("mov.b64 {%0, %1}, %2;" : "=f"(f.x), "=f"(f.y) : "l"(v));
    return f;
}

// ---- smem addr / TMA bulk / mbarrier helpers ----
__device__ __forceinline__ uint32_t smem_u32(const void* p) {
    return (uint32_t)__cvta_generic_to_shared(p);
}
__device__ __forceinline__ void mbar_init(uint32_t mbar, uint32_t cnt) {
    asm volatile("mbarrier.init.shared.b64 [%0], %1;" :: "r"(mbar), "r"(cnt)
                 : "memory");
}
__device__ __forceinline__ void mbar_expect_tx(uint32_t mbar, uint32_t bytes) {
    asm volatile("mbarrier.arrive.expect_tx.shared.b64 _, [%0], %1;"
                 :: "r"(mbar), "r"(bytes) : "memory");
}
__device__ __forceinline__ void mbar_wait(uint32_t mbar, uint32_t parity) {
    asm volatile(
        "{\n\t.reg .pred P;\n\t"
        "WL%=:\n\t"
        "mbarrier.try_wait.parity.acquire.cta.shared::cta.b64 P, [%0], %1, 0x989680;\n\t"
        "@!P bra WL%=;\n\t}"
        :: "r"(mbar), "r"(parity) : "memory");
}
__device__ __forceinline__ void fence_proxy_async_cta() {
    asm volatile("fence.proxy.async.shared::cta;" ::: "memory");
}
__device__ __forceinline__ void bulk_copy_g2s(uint32_t dst, const void* src,
                                              uint32_t bytes, uint32_t mbar) {
    asm volatile(
        "cp.async.bulk.shared::cta.global.mbarrier::complete_tx::bytes "
        "[%0], [%1], %2, [%3];"
        :: "r"(dst), "l"(src), "r"(bytes), "r"(mbar) : "memory");
}

// ---- mma helpers (fp16 in, fp32 accum) ----
__device__ __forceinline__ void mma16816(float d[4], uint32_t a0, uint32_t a1,
                                         uint32_t a2, uint32_t a3,
                                         uint32_t b0, uint32_t b1) {
    asm volatile(
        "mma.sync.aligned.m16n8k16.row.col.f32.f16.f16.f32 "
        "{%0,%1,%2,%3},{%4,%5,%6,%7},{%8,%9},{%0,%1,%2,%3};"
        : "+f"(d[0]), "+f"(d[1]), "+f"(d[2]), "+f"(d[3])
        : "r"(a0), "r"(a1), "r"(a2), "r"(a3), "r"(b0), "r"(b1));
}
__device__ __forceinline__ void mma1688(float d[4], uint32_t a0, uint32_t a1,
                                        uint32_t b0) {
    asm volatile(
        "mma.sync.aligned.m16n8k8.row.col.f32.f16.f16.f32 "
        "{%0,%1,%2,%3},{%4,%5},{%6},{%0,%1,%2,%3};"
        : "+f"(d[0]), "+f"(d[1]), "+f"(d[2]), "+f"(d[3])
        : "r"(a0), "r"(a1), "r"(b0));
}

// ============================================================================
// Convert x[b][r][i] f32 -> x16[r][b][24] fp16 (i padded with zeros).
// ============================================================================
__global__ void convx_kernel(const float* __restrict__ x) {
    const int r = blockIdx.x;
    const int b = threadIdx.x;
    const float4* src = reinterpret_cast<const float4*>(x + ((size_t)b * R_ + r) * I_);
    __half2 h[12];
#pragma unroll
    for (int q = 0; q < 5; q++) {
        float4 v = src[q];
        h[2 * q]     = __floats2half2_rn(v.x, v.y);
        h[2 * q + 1] = __floats2half2_rn(v.z, v.w);
    }
    h[10] = __floats2half2_rn(0.f, 0.f);
    h[11] = __floats2half2_rn(0.f, 0.f);
    uint4* dst = reinterpret_cast<uint4*>(g_x16 + ((size_t)r * B_ + b) * IP);
    dst[0] = *reinterpret_cast<uint4*>(&h[0]);
    dst[1] = *reinterpret_cast<uint4*>(&h[4]);
    dst[2] = *reinterpret_cast<uint4*>(&h[8]);
}

// ============================================================================
// Convert W[r][c][o][i] f32 -> W16[r][c][o][24] fp16 (padded).
// ============================================================================
__global__ void convw_kernel(const float* __restrict__ W) {
    const int idx = blockIdx.x * 256 + threadIdx.x;   // (r,c,o) flat, 294912
    const float4* src = reinterpret_cast<const float4*>(W + (size_t)idx * I_);
    __half2 h[12];
#pragma unroll
    for (int q = 0; q < 5; q++) {
        float4 v = src[q];
        h[2 * q]     = __floats2half2_rn(v.x, v.y);
        h[2 * q + 1] = __floats2half2_rn(v.z, v.w);
    }
    h[10] = __floats2half2_rn(0.f, 0.f);
    h[11] = __floats2half2_rn(0.f, 0.f);
    uint4* dst = reinterpret_cast<uint4*>(g_W16 + (size_t)idx * IP);
    dst[0] = *reinterpret_cast<uint4*>(&h[0]);
    dst[1] = *reinterpret_cast<uint4*>(&h[4]);
    dst[2] = *reinterpret_cast<uint4*>(&h[8]);
}

// ============================================================================
// u_hat via tensor cores. Block = (r, 8 c's), 256 threads = 8 warps (1 c each).
// ============================================================================
__global__ void __launch_bounds__(256) uhat_mma_kernel() {
    const int r  = blockIdx.x / (C_ / 8);
    const int c0 = (blockIdx.x % (C_ / 8)) * 8;
    __shared__ __align__(16) __half xs[B_ * IP];      // [b][24]  12288B
    __shared__ __align__(16) __half ws[8 * O_ * IP];  // [cc][o][24] 6144B
    const int tid = threadIdx.x;
    const int lane = tid & 31, w = tid >> 5;

    {
        const uint4* gx = reinterpret_cast<const uint4*>(g_x16 + (size_t)r * B_ * IP);
        uint4* sx = reinterpret_cast<uint4*>(xs);
#pragma unroll
        for (int m = 0; m < 3; m++) sx[tid + 256 * m] = gx[tid + 256 * m];
        const uint4* gw = reinterpret_cast<const uint4*>(
            g_W16 + ((size_t)r * C_ + c0) * O_ * IP);
        uint4* sw = reinterpret_cast<uint4*>(ws);
        if (tid < 128) { sw[tid] = gw[tid]; sw[tid + 128] = gw[tid + 128]; }
        else { int t = tid - 128; sw[t + 256] = gw[t + 256]; }
    }
    __syncthreads();

    const uint32_t* xs32 = reinterpret_cast<const uint32_t*>(xs);
    const uint32_t* ws32 = reinterpret_cast<const uint32_t*>(ws);
    __half* uh = reinterpret_cast<__half*>(g_uhat4);

    uint32_t bf[2][3];
#pragma unroll
    for (int nt = 0; nt < 2; nt++) {
        int base = (w * 16 + nt * 8 + (lane >> 2)) * 12 + (lane & 3);
        bf[nt][0] = ws32[base];
        bf[nt][1] = ws32[base + 4];
        bf[nt][2] = ws32[base + 8];
    }

    const int c = c0 + w;
#pragma unroll 4
    for (int bt = 0; bt < 16; bt++) {
        const int row = bt * 16 + (lane >> 2);
        const int a0i = row * 12 + (lane & 3);
        const int a1i = a0i + 96;   // row + 8
        uint32_t a0 = xs32[a0i], a1 = xs32[a1i];
        uint32_t a2 = xs32[a0i + 4], a3 = xs32[a1i + 4];
        uint32_t a4 = xs32[a0i + 8], a5 = xs32[a1i + 8];

#pragma unroll
        for (int nt = 0; nt < 2; nt++) {
            float d[4] = {0.f, 0.f, 0.f, 0.f};
            mma16816(d, a0, a1, a2, a3, bf[nt][0], bf[nt][1]);
            mma1688(d, a4, a5, bf[nt][2]);
            __half2 h01 = __floats2half2_rn(d[0], d[1]);
            __half2 h23 = __floats2half2_rn(d[2], d[3]);
            const int o2 = nt * 8 + (lane & 3) * 2;
            const int blo = row, bhi = row + 8;
            size_t alo = ((size_t)(c * NCH + (blo >> 3))) * TILE_HALFS
                       + (size_t)r * 128 + (blo & 7) * 16 + o2;
            size_t ahi = ((size_t)(c * NCH + (bhi >> 3))) * TILE_HALFS
                       + (size_t)r * 128 + (bhi & 7) * 16 + o2;
            *reinterpret_cast<__half2*>(uh + alo) = h01;
            *reinterpret_cast<__half2*>(uh + ahi) = h23;
        }
    }
}

// ============================================================================
// Softmax over r of accumulated logits -> g_c[c][r]. One block per c.
// ============================================================================
__global__ void softmax_kernel(int it) {
    const int c = blockIdx.x;
    const int tid = threadIdx.x;           // = r
    const int lane = tid & 31, warp = tid >> 5;
    __shared__ float sm[6], ssum[6];

    float lg = 0.f;
    {
        const float4* q0 = reinterpret_cast<const float4*>(&g_part[0][c][tid][0]);
#pragma unroll
        for (int j = 0; j < NCH / 4; j++) {
            float4 v = q0[j];
            lg += v.x + v.y + v.z + v.w;
        }
        if (it == 2) {
            const float4* q1 = reinterpret_cast<const float4*>(&g_part[1][c][tid][0]);
#pragma unroll
            for (int j = 0; j < NCH / 4; j++) {
                float4 v = q1[j];
                lg += v.x + v.y + v.z + v.w;
            }
        }
        lg *= (1.f / B_);
    }

    float m = lg;
#pragma unroll
    for (int ofs = 16; ofs; ofs >>= 1) m = fmaxf(m, __shfl_xor_sync(0xFFFFFFFFu, m, ofs));
    if (lane == 0) sm[warp] = m;
    __syncthreads();
    float mm = sm[0];
#pragma unroll
    for (int w = 1; w < 6; w++) mm = fmaxf(mm, sm[w]);

    float e = expf(lg - mm);
    float s = e;
#pragma unroll
    for (int ofs = 16; ofs; ofs >>= 1) s += __shfl_xor_sync(0xFFFFFFFFu, s, ofs);
    if (lane == 0) ssum[warp] = s;
    __syncthreads();
    float tot = 0.f;
#pragma unroll
    for (int w = 0; w < 6; w++) tot += ssum[w];

    g_c[c * R_ + tid] = e / tot;
}

// ============================================================================
// Persistent fused routing kernel. 304 CTAs x 512 threads, double-buffered
// 48KB tiles loaded via cp.async.bulk (TMA) + mbarrier expect_tx.
// ============================================================================
__global__ void __launch_bounds__(512, 2) fused_kernel(float* __restrict__ out, int it) {
    extern __shared__ __align__(16) uint4 su4[];   // 2 * TILE_U4
    __shared__ float sred[16][16][8];              // 8KB
    __shared__ float svf[BCH * O_];                // v as [b][o]
    __shared__ float sc[R_];
    __shared__ __align__(8) uint64_t mbars[2];

    const int tid = threadIdx.x;
    const int lane = tid & 31, warp = tid >> 5;    // 16 warps
    const uint32_t mb0 = smem_u32(&mbars[0]);
    const uint32_t mb1 = smem_u32(&mbars[1]);
    const uint32_t sbase = smem_u32(su4);

    if (tid == 0) {
        mbar_init(mb0, 1);
        mbar_init(mb1, 1);
        fence_proxy_async_cta();
    }
    __syncthreads();

    // ---- prologue: issue first tile into buffer 0 ----
    if (tid == 0) {
        mbar_expect_tx(mb0, TILE_BYTES);
        bulk_copy_g2s(sbase, g_uhat4 + (size_t)blockIdx.x * TILE_U4,
                      TILE_BYTES, mb0);
    }

    uint32_t ph0 = 0, ph1 = 0;
    int p = 0;
    for (int t = blockIdx.x; t < TILES; t += GRID, p ^= 1) {
        const int c = t >> 5, ch = t & 31;
        const int b0 = ch * BCH;
        const bool has_next = (t + GRID) < TILES;

        // ---- issue next tile into the other buffer ----
        if (has_next && tid == 0) {
            fence_proxy_async_cta();   // order prior generic reads before TMA write
            const uint32_t mbn = p ? mb0 : mb1;
            mbar_expect_tx(mbn, TILE_BYTES);
            bulk_copy_g2s(sbase + (p ^ 1) * TILE_BYTES,
                          g_uhat4 + (size_t)(t + GRID) * TILE_U4,
                          TILE_BYTES, mbn);
        }

        // ---- stage softmax coefficients ----
        if (tid < R_) sc[tid] = (it == 0) ? (1.f / R_) : g_c[c * R_ + tid];

        // ---- wait for current tile ----
        if (p == 0) { mbar_wait(mb0, ph0); ph0 ^= 1; }
        else        { mbar_wait(mb1, ph1); ph1 ^= 1; }
        __syncthreads();   // publish sc; all threads past wait

        const uint4* sub = su4 + p * TILE_U4;

        // ---- phase 1: s[b,o] = sum_r sc[r]*u[r,b,o], LDS.128 per thread ----
        {
            const int rg = tid >> 4;      // 0..31, r = rg*6 + j
            const int q  = tid & 15;      // uint4 within row
            unsigned long long acc[4] = {0ULL, 0ULL, 0ULL, 0ULL};
#pragma unroll
            for (int j = 0; j < 6; j++) {
                const int r = rg * 6 + j;
                uint4 u4 = sub[r * 16 + q];
                const __half2* h = reinterpret_cast<const __half2*>(&u4);
                unsigned long long cv = pack2(sc[r]);
#pragma unroll
                for (int s = 0; s < 4; s++) {
                    float2 uf = __half22float2(h[s]);
                    unsigned long long u2;
                    asm("mov.b64 %0, {%1, %2};" : "=l"(u2) : "f"(uf.x), "f"(uf.y));
                    fma2(acc[s], u2, cv);
                }
            }
            float af[8];
#pragma unroll
            for (int s = 0; s < 4; s++) {
                float2 f = unpack2(acc[s]);
                af[2 * s] = f.x; af[2 * s + 1] = f.y;
            }
#pragma unroll
            for (int s = 0; s < 8; s++)
                af[s] += __shfl_xor_sync(0xFFFFFFFFu, af[s], 16);
            if (lane < 16) {
#pragma unroll
                for (int s = 0; s < 8; s++) sred[warp][q][s] = af[s];
            }
        }
        __syncthreads();

        // ---- reduce over 16 groups + squash (128 threads) ----
        if (tid < 128) {
            const int q = tid >> 3, sl = tid & 7;
            float s = 0.f;
#pragma unroll
            for (int g = 0; g < 16; g++) s += sred[g][q][sl];
            const int b = q >> 1;
            const int o = (q & 1) * 8 + sl;
            float n2 = s * s;
#pragma unroll
            for (int ofs = 1; ofs < 16; ofs <<= 1)
                n2 += __shfl_xor_sync(0xFFFFFFFFu, n2, ofs);
            float scale = sqrtf(n2) / (1.f + n2);
            s *= scale;
            if (it == 2)
                out[(((size_t)(b0 + b)) * C_ + c) * O_ + o] = s;
            else
                svf[b * O_ + o] = s;
        }
        __syncthreads();

        // ---- phase 2: a[r] = sum_{b,o} u[r,b,o]*v[b,o] (tile from SMEM) ----
        if (it != 2) {
            const int q  = lane & 15;
            const int rh = lane >> 4;     // 0 or 1
            const float2* sv2 = reinterpret_cast<const float2*>(svf);
            float2 vv[4];
#pragma unroll
            for (int j = 0; j < 4; j++)
                vv[j] = sv2[(q >> 1) * 8 + (q & 1) * 4 + j];

#pragma unroll
            for (int k = 0; k < 6; k++) {
                const int r = warp + 16 * (2 * k + rh);
                uint4 u4 = sub[r * 16 + q];
                const __half2* h = reinterpret_cast<const __half2*>(&u4);
                float pacc = 0.f;
#pragma unroll
                for (int j = 0; j < 4; j++) {
                    float2 uf = __half22float2(h[j]);
                    pacc = fmaf(uf.x, vv[j].x, pacc);
                    pacc = fmaf(uf.y, vv[j].y, pacc);
                }
#pragma unroll
                for (int ofs = 8; ofs; ofs >>= 1)
                    pacc += __shfl_xor_sync(0xFFFFFFFFu, pacc, ofs);
                if ((lane & 15) == 0) g_part[it][c][r][ch] = pacc;
            }
        }
        __syncthreads();   // all reads of buffer p done before its reuse
    }
}

extern "C" void kernel_launch(void* const* d_in, const int* in_sizes, int n_in,
                              void* d_out, int out_size) {
    const float* x = (const float*)d_in[0];  // [B,R,I]
    const float* W = (const float*)d_in[1];  // [R,C,O,I]
    float* out = (float*)d_out;              // [B,C,O]

    const int smem = 2 * TILE_U4 * sizeof(uint4);   // 98304
    cudaFuncSetAttribute(fused_kernel, cudaFuncAttributeMaxDynamicSharedMemorySize, smem);

    convx_kernel<<<R_, 256>>>(x);
    convw_kernel<<<(R_ * C_ * O_) / 256, 256>>>(W);
    uhat_mma_kernel<<<R_ * (C_ / 8), 256>>>();

    for (int it = 0; it < 3; it++) {
        if (it > 0) softmax_kernel<<<C_, 192>>>(it);
        fused_kernel<<<GRID, 512, smem>>>(out, it);
    }
}